// round 13
// baseline (speedup 1.0000x reference)
#include <cuda_runtime.h>
#include <cuda.h>
#include <cuda_fp16.h>
#include <math.h>
#include <stdint.h>
#include <dlfcn.h>

// ---------------- problem constants ----------------
#define QN    16
#define C0N   8
#define C1N   4
#define K3T   125
#define NCH   320
#define VOX   512
#define GK    8
#define NSTG  2

// HMMA K-space: taps 0..108 x ci-blocks 1..4  (436 chunks, 69.8%)
#define NCHUNK_H 436
// FFMA K-space (units of (ci,tap)): ci 0..63 all taps + ci 64..319 taps 109..124
#define UF_TOTAL 12096      // 64*125 + 256*16

// smem stage layout (bytes) after 1KB header (HMMA path)
#define SOFF_A 0
#define SOFF_B 8192
#define STAGE_BYTES 40960
#define HDR 1024
#define SMEM_TOTAL (HDR + NSTG * STAGE_BYTES)

// FFMA path smem strides (R1-verified conflict-free padding)
#define SY 13
#define SZ 168

// ---------------- device globals ----------------
__device__ __half gA[(size_t)K3T * NCH * NCH];    // [tap][och][ci] fp16 (HMMA)
__device__ float  gAf[(size_t)NCH * K3T * NCH];   // [ci][tap][och] fp32 (FFMA)
__device__ __half gXp[1728 * NCH];                // [pz*144+py*12+px][ci]
__device__ float g_part [(size_t)15 * 10 * 64 * 256];  // HMMA partials [sp][tileH][64][256]
__device__ float g_partF[(size_t)15 * 10 * 32 * 512];  // FFMA partials [sp][tileF][32][512]

// ---------------- PTX helpers ----------------
__device__ __forceinline__ uint32_t smem_u32(const void* p) {
    uint32_t a;
    asm("{ .reg .u64 t; cvta.to.shared.u64 t, %1; cvt.u32.u64 %0, t; }" : "=r"(a) : "l"(p));
    return a;
}
__device__ __forceinline__ void ldm4(uint32_t& r0, uint32_t& r1, uint32_t& r2,
                                     uint32_t& r3, uint32_t addr) {
    asm volatile("ldmatrix.sync.aligned.m8n8.x4.shared.b16 {%0,%1,%2,%3}, [%4];"
                 : "=r"(r0), "=r"(r1), "=r"(r2), "=r"(r3) : "r"(addr));
}
__device__ __forceinline__ void mma16816(float* c, uint32_t a0, uint32_t a1,
                                         uint32_t a2, uint32_t a3,
                                         uint32_t b0, uint32_t b1) {
    asm volatile("mma.sync.aligned.m16n8k16.row.col.f32.f16.f16.f32 "
                 "{%0,%1,%2,%3}, {%4,%5,%6,%7}, {%8,%9}, {%0,%1,%2,%3};"
                 : "+f"(c[0]), "+f"(c[1]), "+f"(c[2]), "+f"(c[3])
                 : "r"(a0), "r"(a1), "r"(a2), "r"(a3), "r"(b0), "r"(b1));
}
__device__ __forceinline__ void mbar_init(uint32_t a, uint32_t n) {
    asm volatile("mbarrier.init.shared.b64 [%0], %1;" :: "r"(a), "r"(n) : "memory");
}
__device__ __forceinline__ void mbar_expect_tx(uint32_t a, uint32_t bytes) {
    asm volatile("mbarrier.arrive.expect_tx.shared.b64 _, [%0], %1;"
                 :: "r"(a), "r"(bytes) : "memory");
}
__device__ __forceinline__ void mbar_arrive(uint32_t a) {
    asm volatile("mbarrier.arrive.shared.b64 _, [%0];" :: "r"(a) : "memory");
}
__device__ __forceinline__ void mbar_wait(uint32_t mbar, uint32_t parity) {
    uint32_t done;
    asm volatile("{\n\t.reg .pred p;\n\t"
                 "mbarrier.try_wait.parity.acquire.cta.shared::cta.b64 p, [%1], %2;\n\t"
                 "selp.b32 %0, 1, 0, p;\n\t}"
                 : "=r"(done) : "r"(mbar), "r"(parity) : "memory");
    if (!done) {
        asm volatile("{\n\t.reg .pred P1;\n\t"
                     "W%=:\n\t"
                     "mbarrier.try_wait.parity.acquire.cta.shared::cta.b64 P1, [%0], %1, 0x989680;\n\t"
                     "@P1 bra.uni D%=;\n\t"
                     "bra.uni W%=;\n\t"
                     "D%=:\n\t}"
                     :: "r"(mbar), "r"(parity) : "memory");
    }
}
__device__ __forceinline__ void tma3d(uint32_t dst, const void* map,
                                      int c0, int c1, int c2, uint32_t mbar) {
    asm volatile("cp.async.bulk.tensor.3d.shared::cta.global.tile.mbarrier::complete_tx::bytes "
                 "[%0], [%1, {%2, %3, %4}], [%5];"
                 :: "r"(dst), "l"(map), "r"(c0), "r"(c1), "r"(c2), "r"(mbar) : "memory");
}
__device__ __forceinline__ void tma4d(uint32_t dst, const void* map,
                                      int c0, int c1, int c2, int c3, uint32_t mbar) {
    asm volatile("cp.async.bulk.tensor.4d.shared::cta.global.tile.mbarrier::complete_tx::bytes "
                 "[%0], [%1, {%2, %3, %4, %5}], [%6];"
                 :: "r"(dst), "l"(map), "r"(c0), "r"(c1), "r"(c2), "r"(c3), "r"(mbar) : "memory");
}

// ---------------------------------------------------------------------------
// Kernel 1: x -> transposed + halo-padded fp16 [1728 pos][320 ci]
// ---------------------------------------------------------------------------
__global__ void xpad_kernel(const float* __restrict__ x) {
    int i = blockIdx.x * blockDim.x + threadIdx.x;
    if (i >= 1728 * NCH) return;
    int ci = i % NCH, ppos = i / NCH;
    int px = ppos % 12, py = (ppos / 12) % 12, pz = ppos / 144;
    int z = pz - 2, y = py - 2, xx = px - 2;
    float v = 0.f;
    if ((unsigned)z < 8 && (unsigned)y < 8 && (unsigned)xx < 8)
        v = x[ci * VOX + z * 64 + y * 8 + xx];
    gXp[i] = __float2half(v);
}

// ---------------------------------------------------------------------------
// Kernel 2: build kernel -> gA fp16 [tap][och][ci] + gAf fp32 [ci][tap][och]
// ---------------------------------------------------------------------------
__global__ void build_kern_kernel(const float* __restrict__ q_in,
                                  const float* __restrict__ q_out,
                                  const float* __restrict__ w_ss,
                                  const float* __restrict__ w_vs,
                                  const float* __restrict__ w_sv,
                                  const float* __restrict__ w_vv0,
                                  const float* __restrict__ w_vv1) {
    int idx = blockIdx.x * blockDim.x + threadIdx.x;
    if (idx >= QN * QN * K3T) return;
    int t = idx % K3T;
    int q = (idx / K3T) % QN;
    int p = idx / (K3T * QN);
    int path = blockIdx.y;

    int dz = t / 25, dy = (t / 5) % 5, dx = t % 5;
    float v0 = (float)(dz - 2) - (q_out[p * 3 + 0] - q_in[q * 3 + 0]);
    float v1 = (float)(dy - 2) - (q_out[p * 3 + 1] - q_in[q * 3 + 1]);
    float v2 = (float)(dx - 2) - (q_out[p * 3 + 2] - q_in[q * 3 + 2]);
    float r  = sqrtf(v0 * v0 + v1 * v1 + v2 * v2);
    float inv = (r > 1e-6f) ? (1.0f / r) : 0.0f;
    float u[3] = {v0 * inv, v1 * inv, v2 * inv};

    const float sigma = 5.5f / 7.0f;
    float R[GK];
#pragma unroll
    for (int g = 0; g < GK; g++) {
        float d = (r - sigma * (float)g) / sigma;
        R[g] = expf(-0.5f * d * d);
    }

    float cross[3][3];
    cross[0][0] = 0.f;    cross[0][1] = -u[2];  cross[0][2] =  u[1];
    cross[1][0] =  u[2];  cross[1][1] = 0.f;    cross[1][2] = -u[0];
    cross[2][0] = -u[1];  cross[2][1] =  u[0];  cross[2][2] = 0.f;

#define KSTORE(row, col, val) do {                                            \
    float _v = (val);                                                         \
    gA[((size_t)t * NCH + ((row) * QN + p)) * NCH + ((col) * QN + q)] =       \
        __float2half(_v);                                                     \
    gAf[((size_t)(((col) * QN + q)) * K3T + t) * NCH + ((row) * QN + p)] = _v;\
    } while (0)

    if (path == 0) {
        for (int a = 0; a < C0N; a++)
            for (int c = 0; c < C0N; c++) {
                float s = 0.f;
#pragma unroll
                for (int g = 0; g < GK; g++) s += w_ss[(a * C0N + c) * GK + g] * R[g];
                KSTORE(a, c, s);
            }
    } else if (path == 1) {
        for (int a = 0; a < C0N; a++)
            for (int c = 0; c < C1N; c++) {
                float s = 0.f;
#pragma unroll
                for (int g = 0; g < GK; g++) s += w_sv[(a * C1N + c) * GK + g] * R[g];
#pragma unroll
                for (int j = 0; j < 3; j++) KSTORE(a, 8 + c * 3 + j, s * u[j]);
            }
    } else if (path == 2) {
        for (int a = 0; a < C1N; a++)
            for (int c = 0; c < C0N; c++) {
                float s = 0.f;
#pragma unroll
                for (int g = 0; g < GK; g++) s += w_vs[(a * C0N + c) * GK + g] * R[g];
#pragma unroll
                for (int m = 0; m < 3; m++) KSTORE(8 + a * 3 + m, c, s * u[m]);
            }
    } else {
        for (int a = 0; a < C1N; a++)
            for (int c = 0; c < C1N; c++) {
                float d0 = 0.f, d1 = 0.f;
#pragma unroll
                for (int g = 0; g < GK; g++) {
                    d0 += w_vv0[(a * C1N + c) * GK + g] * R[g];
                    d1 += w_vv1[(a * C1N + c) * GK + g] * R[g];
                }
#pragma unroll
                for (int i = 0; i < 3; i++)
#pragma unroll
                    for (int j = 0; j < 3; j++) {
                        float val = ((i == j) ? d0 : 0.f)
                                  + 0.7071067811865476f * d1 * cross[i][j];
                        KSTORE(8 + a * 3 + i, 8 + c * 3 + j, val);
                    }
            }
    }
#undef KSTORE
}

// ---------------------------------------------------------------------------
// Kernel 3: HYBRID GEMM. grid = 296 linear CTAs, block = 288.
//  bid <  148: HMMA path (tile = bid%10, sp = bid/10; taps 0..108 x blk 1..4)
//  bid >= 148: FFMA path (tileF = fid%10 [32-och], spF = fid/10; fp32 exact)
// Classic placement maps bid and bid+148 to the same SM -> 1 HMMA + 1 FFMA
// CTA per SM, overlapping the tensor and FMA pipes.
// ---------------------------------------------------------------------------
__device__ __forceinline__ void issue_chunk_h(int c, uint32_t sbase, uint32_t mbar,
                                              const void* tA, const void* tB,
                                              int och0, int z0) {
    int t   = c >> 2;                     // tap 0..108
    int ci0 = 64 + ((c & 3) << 6);        // ci-blocks 1..4
    int dz = t / 25, r2 = t - dz * 25;
    int dy = r2 / 5, dx = r2 - dy * 5;
    mbar_expect_tx(mbar, STAGE_BYTES);
    tma3d(sbase + SOFF_A, tA, ci0, och0, t, mbar);
    tma4d(sbase + SOFF_B, tB, ci0, dx, dy, z0 + dz, mbar);
}

__global__ void __launch_bounds__(288, 2)
gemm_hybrid(const __grid_constant__ CUtensorMap tA,
            const __grid_constant__ CUtensorMap tB,
            const float* __restrict__ x) {
    extern __shared__ __align__(1024) char smem[];
    const int bid = blockIdx.x;
    const int tid = threadIdx.x;

    if (bid < 148) {
        // ================= HMMA path =================
        const uint32_t sb = smem_u32(smem);
        const int wid = tid >> 5, lane = tid & 31;
        const int tile = bid % 10, sp = bid / 10;
        const int nsH = (tile < 8) ? 15 : 14;
        const int mt = tile >> 1, nt = tile & 1;
        const int och0 = mt * 64, z0 = nt * 4;
        const int c0 = sp * NCHUNK_H / nsH;
        const int c1 = (sp + 1) * NCHUNK_H / nsH;
        const int n  = c1 - c0;

        const uint32_t fullb  = sb;
        const uint32_t emptyb = sb + 16;
        const uint32_t st0 = sb + HDR;

        if (tid == 0) {
            mbar_init(fullb,      1);   mbar_init(fullb + 8,  1);
            mbar_init(emptyb,     256); mbar_init(emptyb + 8, 256);
        }
        asm volatile("fence.proxy.async.shared::cta;" ::: "memory");
        __syncthreads();

        if (wid == 8) {
            if (lane == 0) {
                for (int j = 0; j < n; j++) {
                    const int s = j & 1;
                    if (j >= NSTG)
                        mbar_wait(emptyb + 8 * s, ((j - NSTG) >> 1) & 1);
                    issue_chunk_h(c0 + j, st0 + (uint32_t)s * STAGE_BYTES,
                                  fullb + 8 * s, &tA, &tB, och0, z0);
                }
            }
            return;
        }

        const int warp_m = wid >> 2, warp_n = wid & 3;
        const int m0 = warp_m * 32, n0 = warp_n * 64;
        const int quad = lane >> 3, r8 = lane & 7;
        const int a_row = (quad & 1) * 8 + r8;
        const int a_sel = quad >> 1;
        const int b_grp = quad >> 1;
        const int b_sel = quad & 1;
        const uint32_t pa0 = (uint32_t)((m0 + a_row) * 128);
        const uint32_t pa1 = (uint32_t)((m0 + 16 + a_row) * 128);
        uint32_t pb[4];
#pragma unroll
        for (int j2 = 0; j2 < 4; j2++)
            pb[j2] = (uint32_t)((n0 + j2 * 16 + b_grp * 8 + r8) * 128);

        float acc[2][8][4];
#pragma unroll
        for (int mi = 0; mi < 2; mi++)
#pragma unroll
            for (int nj = 0; nj < 8; nj++)
#pragma unroll
                for (int e = 0; e < 4; e++) acc[mi][nj][e] = 0.f;

        for (int i = 0; i < n; i++) {
            const int s = i & 1;
            const uint32_t sbase = st0 + (uint32_t)s * STAGE_BYTES;
            mbar_wait(fullb + 8 * s, (i >> 1) & 1);
#pragma unroll
            for (int g = 0; g < 4; g++) {
                const uint32_t aoff = (uint32_t)((((g << 1) + a_sel) ^ r8) << 4);
                const uint32_t boff = (uint32_t)((((g << 1) + b_sel) ^ r8) << 4);
                uint32_t a0[4], a1[4];
                ldm4(a0[0], a0[1], a0[2], a0[3], sbase + SOFF_A + pa0 + aoff);
                ldm4(a1[0], a1[1], a1[2], a1[3], sbase + SOFF_A + pa1 + aoff);
#pragma unroll
                for (int j2 = 0; j2 < 4; j2++) {
                    uint32_t b[4];
                    ldm4(b[0], b[1], b[2], b[3], sbase + SOFF_B + pb[j2] + boff);
                    mma16816(acc[0][2 * j2],     a0[0], a0[1], a0[2], a0[3], b[0], b[1]);
                    mma16816(acc[0][2 * j2 + 1], a0[0], a0[1], a0[2], a0[3], b[2], b[3]);
                    mma16816(acc[1][2 * j2],     a1[0], a1[1], a1[2], a1[3], b[0], b[1]);
                    mma16816(acc[1][2 * j2 + 1], a1[0], a1[1], a1[2], a1[3], b[2], b[3]);
                }
            }
            mbar_arrive(emptyb + 8 * s);
        }

        float* dst = g_part + (size_t)(sp * 10 + tile) * (64 * 256);
        const int gidx = lane >> 2, tid4 = lane & 3;
#pragma unroll
        for (int mi = 0; mi < 2; mi++)
#pragma unroll
            for (int nj = 0; nj < 8; nj++) {
                int row = m0 + 16 * mi + gidx;
                int col = n0 + 8 * nj + tid4 * 2;
                *(float2*)(dst + row * 256 + col) =
                    make_float2(acc[mi][nj][0], acc[mi][nj][1]);
                *(float2*)(dst + (row + 8) * 256 + col) =
                    make_float2(acc[mi][nj][2], acc[mi][nj][3]);
            }
        return;
    }

    // ================= FFMA path (fp32 exact, R1-derived) =================
    if (tid >= 256) return;
    const int fid = bid - 148;
    const int tileF = fid % 10, spF = fid / 10;
    const int nsF = (tileF < 8) ? 15 : 14;
    const int och0F = tileF * 32;
    const int u0 = spF * UF_TOTAL / nsF;
    const int u1 = (spF + 1) * UF_TOTAL / nsF;

    float* xp = (float*)smem;                 // 12*SZ floats (8064B)
    float* ks = (float*)(smem + 8064);        // up to 125*32 floats (16000B)

    const int o_sub = tid >> 6;               // 0..3
    const int v_sub = tid & 63;
    const int z = v_sub >> 3, y = v_sub & 7;

    float acc[8][8];
#pragma unroll
    for (int o = 0; o < 8; o++)
#pragma unroll
        for (int i = 0; i < 8; i++) acc[o][i] = 0.f;

    for (int i = tid; i < 12 * SZ; i += 256) xp[i] = 0.f;

    int u = u0;
    while (u < u1) {
        int ci, t0;
        if (u < 8000) { ci = u / 125; t0 = u - ci * 125; }
        else { int v2 = u - 8000; ci = 64 + (v2 >> 4); t0 = 109 + (v2 & 15); }
        int t1 = t0 + (u1 - u);
        if (t1 > 125) t1 = 125;
        const int L = t1 - t0;

        __syncthreads();
        for (int i = tid; i < VOX; i += 256) {
            int zz = i >> 6, yy = (i >> 3) & 7, xx = i & 7;
            xp[(zz + 2) * SZ + (yy + 2) * SY + (xx + 2)] = x[ci * VOX + i];
        }
        for (int i = tid; i < 32 * L; i += 256) {
            int tr = i >> 5, o = i & 31;
            ks[tr * 32 + o] = gAf[((size_t)ci * K3T + (t0 + tr)) * NCH + och0F + o];
        }
        __syncthreads();

        const int base0 = z * SZ + y * SY;
        for (int tr = 0; tr < L; tr++) {
            int t = t0 + tr;
            int dz5 = t / 25, r2 = t - dz5 * 25;
            int dy5 = r2 / 5, dx5 = r2 - dy5 * 5;
            const float* xrow = &xp[base0 + dz5 * SZ + dy5 * SY + dx5];
            float xv[8];
#pragma unroll
            for (int i = 0; i < 8; i++) xv[i] = xrow[i];
            const float* kp = &ks[tr * 32 + o_sub * 8];
#pragma unroll
            for (int o = 0; o < 8; o++) {
                float kv = kp[o];
#pragma unroll
                for (int i = 0; i < 8; i++) acc[o][i] += kv * xv[i];
            }
        }
        u += L;
    }

    float* dst = g_partF + (size_t)(spF * 10 + tileF) * (32 * 512);
#pragma unroll
    for (int o = 0; o < 8; o++) {
        float* dp = dst + (o_sub * 8 + o) * 512 + v_sub * 8;
        *(float4*)(dp)     = make_float4(acc[o][0], acc[o][1], acc[o][2], acc[o][3]);
        *(float4*)(dp + 4) = make_float4(acc[o][4], acc[o][5], acc[o][6], acc[o][7]);
    }
}

// ---------------------------------------------------------------------------
// Kernel 4: reduce HMMA + FFMA partials + bias (float4).
// ---------------------------------------------------------------------------
__global__ void reduce_kernel(float* __restrict__ out,
                              const float* __restrict__ bias) {
    int idx = blockIdx.x * blockDim.x + threadIdx.x;
    if (idx >= NCH * VOX / 4) return;
    int i = idx * 4;
    int och = i >> 9, v = i & 511;

    float4 s = make_float4(0.f, 0.f, 0.f, 0.f);
    // HMMA partials
    {
        int mt = och >> 6, nt = v >> 8;
        int tileH = mt * 2 + nt;
        int nsH = (tileH < 8) ? 15 : 14;
        const float* src = g_part + (size_t)tileH * (64 * 256)
                         + (och & 63) * 256 + (v & 255);
        for (int sp = 0; sp < nsH; sp++) {
            float4 t = *(const float4*)(src + (size_t)sp * 10 * 64 * 256);
            s.x += t.x; s.y += t.y; s.z += t.z; s.w += t.w;
        }
    }
    // FFMA partials
    {
        int tileF = och >> 5;
        int nsF = (tileF < 8) ? 15 : 14;
        const float* src = g_partF + (size_t)tileF * (32 * 512)
                         + (och & 31) * 512 + v;
        for (int sp = 0; sp < nsF; sp++) {
            float4 t = *(const float4*)(src + (size_t)sp * 10 * 32 * 512);
            s.x += t.x; s.y += t.y; s.z += t.z; s.w += t.w;
        }
    }
    int d = och >> 4;
    if (d < C0N) {
        float b = bias[d];
        s.x += b; s.y += b; s.z += b; s.w += b;
    }
    *(float4*)(out + i) = s;
}

// ---------------------------------------------------------------------------
typedef CUresult (*EncodeFn)(CUtensorMap*, CUtensorMapDataType, cuuint32_t, void*,
                             const cuuint64_t*, const cuuint64_t*, const cuuint32_t*,
                             const cuuint32_t*, CUtensorMapInterleave, CUtensorMapSwizzle,
                             CUtensorMapL2promotion, CUtensorMapFloatOOBfill);

static void make_map_3d(EncodeFn enc, CUtensorMap* m, void* base) {
    cuuint64_t dims[3]    = {NCH, NCH, K3T};
    cuuint64_t strides[2] = {NCH * 2ull, (cuuint64_t)NCH * NCH * 2ull};
    cuuint32_t box[3]     = {64, 64, 1};
    cuuint32_t es[3]      = {1, 1, 1};
    enc(m, CU_TENSOR_MAP_DATA_TYPE_FLOAT16, 3, base, dims, strides, box, es,
        CU_TENSOR_MAP_INTERLEAVE_NONE, CU_TENSOR_MAP_SWIZZLE_128B,
        CU_TENSOR_MAP_L2_PROMOTION_L2_128B, CU_TENSOR_MAP_FLOAT_OOB_FILL_NONE);
}
static void make_map_4d(EncodeFn enc, CUtensorMap* m, void* base) {
    cuuint64_t dims[4]    = {NCH, 12, 12, 12};
    cuuint64_t strides[3] = {NCH * 2ull, NCH * 12 * 2ull, NCH * 144 * 2ull};
    cuuint32_t box[4]     = {64, 8, 8, 4};
    cuuint32_t es[4]      = {1, 1, 1, 1};
    enc(m, CU_TENSOR_MAP_DATA_TYPE_FLOAT16, 4, base, dims, strides, box, es,
        CU_TENSOR_MAP_INTERLEAVE_NONE, CU_TENSOR_MAP_SWIZZLE_128B,
        CU_TENSOR_MAP_L2_PROMOTION_L2_128B, CU_TENSOR_MAP_FLOAT_OOB_FILL_NONE);
}

extern "C" void kernel_launch(void* const* d_in, const int* in_sizes, int n_in,
                              void* d_out, int out_size) {
    const float* x     = (const float*)d_in[0];
    const float* q_in  = (const float*)d_in[1];
    const float* q_out = (const float*)d_in[2];
    const float* w_ss  = (const float*)d_in[3];
    const float* w_vs  = (const float*)d_in[4];
    const float* w_sv  = (const float*)d_in[5];
    const float* w_vv0 = (const float*)d_in[6];
    const float* w_vv1 = (const float*)d_in[7];
    const float* bias  = (const float*)d_in[8];
    float* out = (float*)d_out;

    void* lib = dlopen("libcuda.so.1", RTLD_LAZY | RTLD_GLOBAL);
    EncodeFn enc = lib ? (EncodeFn)dlsym(lib, "cuTensorMapEncodeTiled") : nullptr;

    void *pA, *pB;
    cudaGetSymbolAddress(&pA, gA);
    cudaGetSymbolAddress(&pB, gXp);

    CUtensorMap mA, mB;
    make_map_3d(enc, &mA, pA);
    make_map_4d(enc, &mB, pB);

    xpad_kernel<<<(1728 * NCH + 255) / 256, 256>>>(x);

    dim3 bgrid((QN * QN * K3T + 255) / 256, 4);
    build_kern_kernel<<<bgrid, 256>>>(q_in, q_out, w_ss, w_vs, w_sv, w_vv0, w_vv1);

    cudaFuncSetAttribute(gemm_hybrid, cudaFuncAttributeMaxDynamicSharedMemorySize, SMEM_TOTAL);
    gemm_hybrid<<<296, 288, SMEM_TOTAL>>>(mA, mB, x);

    reduce_kernel<<<(NCH * VOX / 4 + 255) / 256, 256>>>(out, bias);
}

// round 14
// speedup vs baseline: 2.4224x; 2.4224x over previous
#include <cuda_runtime.h>
#include <cuda.h>
#include <cuda_fp16.h>
#include <math.h>
#include <stdint.h>
#include <dlfcn.h>

// ---------------- problem constants ----------------
#define QN    16
#define C0N   8
#define C1N   4
#define K3T   125
#define NCH   320
#define VOX   512
#define GK    8
#define NSPL  29
#define NCHUNK 625          // 125 taps * 5 ci-blocks of 64
#define NSTG  2             // double buffer

// smem stage layout (bytes) after 1KB header
#define SOFF_A 0
#define SOFF_B 8192
#define STAGE_BYTES 40960
#define HDR 1024
#define SMEM_TOTAL (HDR + NSTG * STAGE_BYTES)

// ---------------- device globals ----------------
__device__ __half gA[(size_t)K3T * NCH * NCH];   // [tap][och][ci]
__device__ __half gXp[1728 * NCH];               // [pz*144+py*12+px][ci]
__device__ float g_part[(size_t)NSPL * 10 * 64 * 256];

// ---------------- PTX helpers ----------------
__device__ __forceinline__ uint32_t smem_u32(const void* p) {
    uint32_t a;
    asm("{ .reg .u64 t; cvta.to.shared.u64 t, %1; cvt.u32.u64 %0, t; }" : "=r"(a) : "l"(p));
    return a;
}
__device__ __forceinline__ void ldm4(uint32_t& r0, uint32_t& r1, uint32_t& r2,
                                     uint32_t& r3, uint32_t addr) {
    asm volatile("ldmatrix.sync.aligned.m8n8.x4.shared.b16 {%0,%1,%2,%3}, [%4];"
                 : "=r"(r0), "=r"(r1), "=r"(r2), "=r"(r3) : "r"(addr));
}
__device__ __forceinline__ void mma16816(float* c, uint32_t a0, uint32_t a1,
                                         uint32_t a2, uint32_t a3,
                                         uint32_t b0, uint32_t b1) {
    asm volatile("mma.sync.aligned.m16n8k16.row.col.f32.f16.f16.f32 "
                 "{%0,%1,%2,%3}, {%4,%5,%6,%7}, {%8,%9}, {%0,%1,%2,%3};"
                 : "+f"(c[0]), "+f"(c[1]), "+f"(c[2]), "+f"(c[3])
                 : "r"(a0), "r"(a1), "r"(a2), "r"(a3), "r"(b0), "r"(b1));
}
__device__ __forceinline__ void mbar_init(uint32_t a, uint32_t n) {
    asm volatile("mbarrier.init.shared.b64 [%0], %1;" :: "r"(a), "r"(n) : "memory");
}
__device__ __forceinline__ void mbar_expect_tx(uint32_t a, uint32_t bytes) {
    asm volatile("mbarrier.arrive.expect_tx.shared.b64 _, [%0], %1;"
                 :: "r"(a), "r"(bytes) : "memory");
}
__device__ __forceinline__ void mbar_arrive(uint32_t a) {
    asm volatile("mbarrier.arrive.shared.b64 _, [%0];" :: "r"(a) : "memory");
}
__device__ __forceinline__ void mbar_wait(uint32_t mbar, uint32_t parity) {
    uint32_t done;
    asm volatile("{\n\t.reg .pred p;\n\t"
                 "mbarrier.try_wait.parity.acquire.cta.shared::cta.b64 p, [%1], %2;\n\t"
                 "selp.b32 %0, 1, 0, p;\n\t}"
                 : "=r"(done) : "r"(mbar), "r"(parity) : "memory");
    if (!done) {
        asm volatile("{\n\t.reg .pred P1;\n\t"
                     "W%=:\n\t"
                     "mbarrier.try_wait.parity.acquire.cta.shared::cta.b64 P1, [%0], %1, 0x989680;\n\t"
                     "@P1 bra.uni D%=;\n\t"
                     "bra.uni W%=;\n\t"
                     "D%=:\n\t}"
                     :: "r"(mbar), "r"(parity) : "memory");
    }
}
__device__ __forceinline__ void tma3d(uint32_t dst, const void* map,
                                      int c0, int c1, int c2, uint32_t mbar) {
    asm volatile("cp.async.bulk.tensor.3d.shared::cta.global.tile.mbarrier::complete_tx::bytes "
                 "[%0], [%1, {%2, %3, %4}], [%5];"
                 :: "r"(dst), "l"(map), "r"(c0), "r"(c1), "r"(c2), "r"(mbar) : "memory");
}
__device__ __forceinline__ void tma4d(uint32_t dst, const void* map,
                                      int c0, int c1, int c2, int c3, uint32_t mbar) {
    asm volatile("cp.async.bulk.tensor.4d.shared::cta.global.tile.mbarrier::complete_tx::bytes "
                 "[%0], [%1, {%2, %3, %4, %5}], [%6];"
                 :: "r"(dst), "l"(map), "r"(c0), "r"(c1), "r"(c2), "r"(c3), "r"(mbar) : "memory");
}

// ---------------------------------------------------------------------------
// Kernel 1: x -> transposed + halo-padded fp16 [1728 pos][320 ci]
// ---------------------------------------------------------------------------
__global__ void xpad_kernel(const float* __restrict__ x) {
    int i = blockIdx.x * blockDim.x + threadIdx.x;
    if (i >= 1728 * NCH) return;
    int ci = i % NCH, ppos = i / NCH;
    int px = ppos % 12, py = (ppos / 12) % 12, pz = ppos / 144;
    int z = pz - 2, y = py - 2, xx = px - 2;
    float v = 0.f;
    if ((unsigned)z < 8 && (unsigned)y < 8 && (unsigned)xx < 8)
        v = x[ci * VOX + z * 64 + y * 8 + xx];
    gXp[i] = __float2half(v);
}

// ---------------------------------------------------------------------------
// Kernel 2: build equivariant kernel -> gA [tap][och][ci] fp16.
// ---------------------------------------------------------------------------
__global__ void build_kern_kernel(const float* __restrict__ q_in,
                                  const float* __restrict__ q_out,
                                  const float* __restrict__ w_ss,
                                  const float* __restrict__ w_vs,
                                  const float* __restrict__ w_sv,
                                  const float* __restrict__ w_vv0,
                                  const float* __restrict__ w_vv1) {
    int idx = blockIdx.x * blockDim.x + threadIdx.x;
    if (idx >= QN * QN * K3T) return;
    int t = idx % K3T;
    int q = (idx / K3T) % QN;
    int p = idx / (K3T * QN);
    int path = blockIdx.y;

    int dz = t / 25, dy = (t / 5) % 5, dx = t % 5;
    float v0 = (float)(dz - 2) - (q_out[p * 3 + 0] - q_in[q * 3 + 0]);
    float v1 = (float)(dy - 2) - (q_out[p * 3 + 1] - q_in[q * 3 + 1]);
    float v2 = (float)(dx - 2) - (q_out[p * 3 + 2] - q_in[q * 3 + 2]);
    float r  = sqrtf(v0 * v0 + v1 * v1 + v2 * v2);
    float inv = (r > 1e-6f) ? (1.0f / r) : 0.0f;
    float u[3] = {v0 * inv, v1 * inv, v2 * inv};

    const float sigma = 5.5f / 7.0f;
    float R[GK];
#pragma unroll
    for (int g = 0; g < GK; g++) {
        float d = (r - sigma * (float)g) / sigma;
        R[g] = expf(-0.5f * d * d);
    }

    float cross[3][3];
    cross[0][0] = 0.f;    cross[0][1] = -u[2];  cross[0][2] =  u[1];
    cross[1][0] =  u[2];  cross[1][1] = 0.f;    cross[1][2] = -u[0];
    cross[2][0] = -u[1];  cross[2][1] =  u[0];  cross[2][2] = 0.f;

#define KSTORE(row, col, val) \
    gA[((size_t)t * NCH + ((row) * QN + p)) * NCH + ((col) * QN + q)] = __float2half(val)

    if (path == 0) {
        for (int a = 0; a < C0N; a++)
            for (int c = 0; c < C0N; c++) {
                float s = 0.f;
#pragma unroll
                for (int g = 0; g < GK; g++) s += w_ss[(a * C0N + c) * GK + g] * R[g];
                KSTORE(a, c, s);
            }
    } else if (path == 1) {
        for (int a = 0; a < C0N; a++)
            for (int c = 0; c < C1N; c++) {
                float s = 0.f;
#pragma unroll
                for (int g = 0; g < GK; g++) s += w_sv[(a * C1N + c) * GK + g] * R[g];
#pragma unroll
                for (int j = 0; j < 3; j++) KSTORE(a, 8 + c * 3 + j, s * u[j]);
            }
    } else if (path == 2) {
        for (int a = 0; a < C1N; a++)
            for (int c = 0; c < C0N; c++) {
                float s = 0.f;
#pragma unroll
                for (int g = 0; g < GK; g++) s += w_vs[(a * C0N + c) * GK + g] * R[g];
#pragma unroll
                for (int m = 0; m < 3; m++) KSTORE(8 + a * 3 + m, c, s * u[m]);
            }
    } else {
        for (int a = 0; a < C1N; a++)
            for (int c = 0; c < C1N; c++) {
                float d0 = 0.f, d1 = 0.f;
#pragma unroll
                for (int g = 0; g < GK; g++) {
                    d0 += w_vv0[(a * C1N + c) * GK + g] * R[g];
                    d1 += w_vv1[(a * C1N + c) * GK + g] * R[g];
                }
#pragma unroll
                for (int i = 0; i < 3; i++)
#pragma unroll
                    for (int j = 0; j < 3; j++) {
                        float val = ((i == j) ? d0 : 0.f)
                                  + 0.7071067811865476f * d1 * cross[i][j];
                        KSTORE(8 + a * 3 + i, 8 + c * 3 + j, val);
                    }
            }
    }
#undef KSTORE
}

// ---------------------------------------------------------------------------
// Kernel 3: fp16 mma.sync split-K implicit GEMM.
// 16 compute warps (2M x 8N, 32x32 warp tile) + 1 producer warp = 544 thr.
// 2 CTAs/SM -> 8 HMMA warps per SMSP (latency-hiding A/B test).
// grid = (10 = 5 M-tiles x 2 N-tiles, NSPL).
// ---------------------------------------------------------------------------
__device__ __forceinline__ void issue_chunk(int c, uint32_t sbase, uint32_t mbar,
                                            const void* tA, const void* tB,
                                            int och0, int z0) {
    int t   = c / 5;
    int ci0 = (c - t * 5) * 64;
    int dz = t / 25, r2 = t - dz * 25;
    int dy = r2 / 5, dx = r2 - dy * 5;
    mbar_expect_tx(mbar, STAGE_BYTES);
    tma3d(sbase + SOFF_A, tA, ci0, och0, t, mbar);
    tma4d(sbase + SOFF_B, tB, ci0, dx, dy, z0 + dz, mbar);
}

__global__ void __launch_bounds__(544, 2)
gemm_mma(const __grid_constant__ CUtensorMap tA,
         const __grid_constant__ CUtensorMap tB) {
    extern __shared__ __align__(1024) char smem[];
    const uint32_t sb = smem_u32(smem);
    const int tid = threadIdx.x;
    const int wid = tid >> 5, lane = tid & 31;

    const int mt = blockIdx.x >> 1;          // 0..4
    const int nt = blockIdx.x & 1;           // 0..1
    const int sp = blockIdx.y;
    const int och0 = mt * 64, z0 = nt * 4;
    const int c0 = (sp * NCHUNK) / NSPL;
    const int c1 = ((sp + 1) * NCHUNK) / NSPL;
    const int n  = c1 - c0;

    const uint32_t fullb  = sb;
    const uint32_t emptyb = sb + 16;
    const uint32_t st0 = sb + HDR;

    if (tid == 0) {
        mbar_init(fullb,      1);   mbar_init(fullb + 8,  1);
        mbar_init(emptyb,     512); mbar_init(emptyb + 8, 512);
    }
    asm volatile("fence.proxy.async.shared::cta;" ::: "memory");
    __syncthreads();

    if (wid == 16) {
        // -------- producer warp --------
        if (lane == 0) {
            for (int j = 0; j < n; j++) {
                const int s = j & 1;
                if (j >= NSTG)
                    mbar_wait(emptyb + 8 * s, ((j - NSTG) >> 1) & 1);
                issue_chunk(c0 + j, st0 + (uint32_t)s * STAGE_BYTES,
                            fullb + 8 * s, &tA, &tB, och0, z0);
            }
        }
        return;
    }

    // -------- compute warps (0-15): 2M x 8N, warp tile 32x32 --------
    const int warp_m = wid >> 3, warp_n = wid & 7;
    const int m0 = warp_m * 32, n0 = warp_n * 32;

    const int quad = lane >> 3, r8 = lane & 7;
    const int a_row = (quad & 1) * 8 + r8;
    const int a_sel = quad >> 1;
    const int b_grp = quad >> 1;
    const int b_sel = quad & 1;
    const uint32_t pa0 = (uint32_t)((m0 + a_row) * 128);
    const uint32_t pa1 = (uint32_t)((m0 + 16 + a_row) * 128);
    uint32_t pb[2];
#pragma unroll
    for (int j2 = 0; j2 < 2; j2++)
        pb[j2] = (uint32_t)((n0 + j2 * 16 + b_grp * 8 + r8) * 128);

    float acc[2][4][4];
#pragma unroll
    for (int mi = 0; mi < 2; mi++)
#pragma unroll
        for (int nj = 0; nj < 4; nj++)
#pragma unroll
            for (int e = 0; e < 4; e++) acc[mi][nj][e] = 0.f;

    for (int i = 0; i < n; i++) {
        const int s = i & 1;
        const uint32_t sbase = st0 + (uint32_t)s * STAGE_BYTES;
        mbar_wait(fullb + 8 * s, (i >> 1) & 1);

#pragma unroll
        for (int g = 0; g < 4; g++) {
            const uint32_t aoff = (uint32_t)((((g << 1) + a_sel) ^ r8) << 4);
            const uint32_t boff = (uint32_t)((((g << 1) + b_sel) ^ r8) << 4);
            uint32_t a0[4], a1[4];
            ldm4(a0[0], a0[1], a0[2], a0[3], sbase + SOFF_A + pa0 + aoff);
            ldm4(a1[0], a1[1], a1[2], a1[3], sbase + SOFF_A + pa1 + aoff);
#pragma unroll
            for (int j2 = 0; j2 < 2; j2++) {
                uint32_t b[4];
                ldm4(b[0], b[1], b[2], b[3], sbase + SOFF_B + pb[j2] + boff);
                mma16816(acc[0][2 * j2],     a0[0], a0[1], a0[2], a0[3], b[0], b[1]);
                mma16816(acc[0][2 * j2 + 1], a0[0], a0[1], a0[2], a0[3], b[2], b[3]);
                mma16816(acc[1][2 * j2],     a1[0], a1[1], a1[2], a1[3], b[0], b[1]);
                mma16816(acc[1][2 * j2 + 1], a1[0], a1[1], a1[2], a1[3], b[2], b[3]);
            }
        }
        mbar_arrive(emptyb + 8 * s);   // 512 compute threads arrive
    }

    // epilogue -> g_part[sp][blockIdx.x][64][256]
    float* dst = g_part + (size_t)(sp * 10 + blockIdx.x) * (64 * 256);
    const int gidx = lane >> 2, tid4 = lane & 3;
#pragma unroll
    for (int mi = 0; mi < 2; mi++)
#pragma unroll
        for (int nj = 0; nj < 4; nj++) {
            int row = m0 + 16 * mi + gidx;
            int col = n0 + 8 * nj + tid4 * 2;
            *(float2*)(dst + row * 256 + col) =
                make_float2(acc[mi][nj][0], acc[mi][nj][1]);
            *(float2*)(dst + (row + 8) * 256 + col) =
                make_float2(acc[mi][nj][2], acc[mi][nj][3]);
        }
}

// ---------------------------------------------------------------------------
// Kernel 4: reduce split partials + bias (float4 vectorized).
// ---------------------------------------------------------------------------
__global__ void reduce_kernel(float* __restrict__ out,
                              const float* __restrict__ bias) {
    int idx = blockIdx.x * blockDim.x + threadIdx.x;   // one float4 per thread
    if (idx >= NCH * VOX / 4) return;
    int i = idx * 4;
    int och = i >> 9, v = i & 511;
    int mt = och >> 6, ro = och & 63;
    int ntl = v >> 8, rv = v & 255;
    int blk = mt * 2 + ntl;
    const float* src = g_part + (size_t)blk * (64 * 256) + ro * 256 + rv;
    float4 s = make_float4(0.f, 0.f, 0.f, 0.f);
#pragma unroll
    for (int sp = 0; sp < NSPL; sp++) {
        float4 t = *(const float4*)(src + (size_t)sp * 10 * 64 * 256);
        s.x += t.x; s.y += t.y; s.z += t.z; s.w += t.w;
    }
    int d = och >> 4;
    if (d < C0N) {
        float b = bias[d];
        s.x += b; s.y += b; s.z += b; s.w += b;
    }
    *(float4*)(out + i) = s;
}

// ---------------------------------------------------------------------------
typedef CUresult (*EncodeFn)(CUtensorMap*, CUtensorMapDataType, cuuint32_t, void*,
                             const cuuint64_t*, const cuuint64_t*, const cuuint32_t*,
                             const cuuint32_t*, CUtensorMapInterleave, CUtensorMapSwizzle,
                             CUtensorMapL2promotion, CUtensorMapFloatOOBfill);

static void make_map_3d(EncodeFn enc, CUtensorMap* m, void* base) {
    cuuint64_t dims[3]    = {NCH, NCH, K3T};
    cuuint64_t strides[2] = {NCH * 2ull, (cuuint64_t)NCH * NCH * 2ull};
    cuuint32_t box[3]     = {64, 64, 1};
    cuuint32_t es[3]      = {1, 1, 1};
    enc(m, CU_TENSOR_MAP_DATA_TYPE_FLOAT16, 3, base, dims, strides, box, es,
        CU_TENSOR_MAP_INTERLEAVE_NONE, CU_TENSOR_MAP_SWIZZLE_128B,
        CU_TENSOR_MAP_L2_PROMOTION_L2_128B, CU_TENSOR_MAP_FLOAT_OOB_FILL_NONE);
}
static void make_map_4d(EncodeFn enc, CUtensorMap* m, void* base) {
    cuuint64_t dims[4]    = {NCH, 12, 12, 12};
    cuuint64_t strides[3] = {NCH * 2ull, NCH * 12 * 2ull, NCH * 144 * 2ull};
    cuuint32_t box[4]     = {64, 8, 8, 4};
    cuuint32_t es[4]      = {1, 1, 1, 1};
    enc(m, CU_TENSOR_MAP_DATA_TYPE_FLOAT16, 4, base, dims, strides, box, es,
        CU_TENSOR_MAP_INTERLEAVE_NONE, CU_TENSOR_MAP_SWIZZLE_128B,
        CU_TENSOR_MAP_L2_PROMOTION_L2_128B, CU_TENSOR_MAP_FLOAT_OOB_FILL_NONE);
}

extern "C" void kernel_launch(void* const* d_in, const int* in_sizes, int n_in,
                              void* d_out, int out_size) {
    const float* x     = (const float*)d_in[0];
    const float* q_in  = (const float*)d_in[1];
    const float* q_out = (const float*)d_in[2];
    const float* w_ss  = (const float*)d_in[3];
    const float* w_vs  = (const float*)d_in[4];
    const float* w_sv  = (const float*)d_in[5];
    const float* w_vv0 = (const float*)d_in[6];
    const float* w_vv1 = (const float*)d_in[7];
    const float* bias  = (const float*)d_in[8];
    float* out = (float*)d_out;

    void* lib = dlopen("libcuda.so.1", RTLD_LAZY | RTLD_GLOBAL);
    EncodeFn enc = lib ? (EncodeFn)dlsym(lib, "cuTensorMapEncodeTiled") : nullptr;

    void *pA, *pB;
    cudaGetSymbolAddress(&pA, gA);
    cudaGetSymbolAddress(&pB, gXp);

    CUtensorMap mA, mB;
    make_map_3d(enc, &mA, pA);
    make_map_4d(enc, &mB, pB);

    xpad_kernel<<<(1728 * NCH + 255) / 256, 256>>>(x);

    dim3 bgrid((QN * QN * K3T + 255) / 256, 4);
    build_kern_kernel<<<bgrid, 256>>>(q_in, q_out, w_ss, w_vs, w_sv, w_vv0, w_vv1);

    cudaFuncSetAttribute(gemm_mma, cudaFuncAttributeMaxDynamicSharedMemorySize, SMEM_TOTAL);
    gemm_mma<<<dim3(10, NSPL), 544, SMEM_TOTAL>>>(mA, mB);

    reduce_kernel<<<(NCH * VOX / 4 + 255) / 256, 256>>>(out, bias);
}